// round 1
// baseline (speedup 1.0000x reference)
#include <cuda_runtime.h>
#include <math.h>

#define BQ   8
#define CQ   96
#define LQ   4096
#define DIQ  192
#define DI2Q 384
#define DSQ  16
#define NCQ  32
#define SCHQ 128

// ---------------- scratch (static device globals; no allocation) ----------------
static __device__ float g_xmt [(size_t)BQ * DIQ * LQ];   // xm transposed (B,192,L)
static __device__ float g_zs  [(size_t)BQ * LQ * DIQ];   // silu(z), later y*silu(z)   (B,L,192)
static __device__ float g_xms [(size_t)BQ * LQ * DIQ];   // silu(conv(xm))             (B,L,192)
static __device__ float g_delta[(size_t)BQ * LQ * DIQ];  // softplus(...)              (B,L,192)
static __device__ float g_Bm  [(size_t)BQ * LQ * DSQ];   // (B,L,16)
static __device__ float g_Cm  [(size_t)BQ * LQ * DSQ];   // (B,L,16)
static __device__ float g_hend[(size_t)BQ * NCQ * DIQ * DSQ];
static __device__ float g_hin [(size_t)BQ * NCQ * DIQ * DSQ];
static __device__ float g_dsum[(size_t)BQ * NCQ * DIQ];

// ---------------- helpers ----------------
__device__ __forceinline__ void pw16f(float p1, float* pw) {
    float p2 = p1 * p1, p4 = p2 * p2, p8 = p4 * p4;
    pw[0] = p1;        pw[1] = p2;        pw[2] = p2 * p1;   pw[3] = p4;
    pw[4] = p4 * p1;   pw[5] = p4 * p2;   pw[6] = p4 * pw[2];pw[7] = p8;
    pw[8] = p8 * p1;   pw[9] = p8 * p2;   pw[10]= p8 * pw[2];pw[11]= p8 * p4;
    pw[12]= p8 * pw[4];pw[13]= p8 * pw[5];pw[14]= p8 * pw[6];pw[15]= p8 * p8;
}

__device__ __forceinline__ bool apat(const float* __restrict__ alog, int e, float* a) {
    #pragma unroll
    for (int n = 0; n < DSQ; n++) a[n] = -expf(alog[e * DSQ + n]);
    bool pat = true;
    #pragma unroll
    for (int n = 1; n < DSQ; n++) {
        float tgt = (float)(n + 1) * a[0];
        pat = pat && (fabsf(a[n] - tgt) <= 1e-4f * (1.f + fabsf(tgt)));
    }
    return pat;
}

__device__ __forceinline__ float siluf(float v) { return v / (1.f + expf(-v)); }

// ---------------- K1: in_proj GEMM + split (xm_t, silu(z)) ----------------
// out[b,l,j] = sum_c x[b,c,l] * W[j,c];  grid (L/128, 384/64, B), 128 thr
__global__ __launch_bounds__(128) void mk_inproj(const float* __restrict__ x,
                                                 const float* __restrict__ w) {
    extern __shared__ float sm[];
    float* Xs = sm;               // [96][128]
    float* Ws = sm + 96 * 128;    // [96][65] transposed+padded
    const int l0 = blockIdx.x * 128;
    const int j0 = blockIdx.y * 64;
    const int b  = blockIdx.z;
    const int tid = threadIdx.x;

    const float* xb = x + (size_t)b * CQ * LQ + l0;
    for (int idx = tid; idx < 96 * 128; idx += 128) {
        int c = idx >> 7, i = idx & 127;
        Xs[idx] = xb[(size_t)c * LQ + i];
    }
    for (int idx = tid; idx < 64 * 96; idx += 128) {
        int j = idx / 96, c = idx - j * 96;
        Ws[c * 65 + j] = w[(size_t)(j0 + j) * 96 + c];
    }
    __syncthreads();

    const int tx = tid & 15, ty = tid >> 4;
    float acc[8][8];
    #pragma unroll
    for (int i = 0; i < 8; i++)
        #pragma unroll
        for (int j = 0; j < 8; j++) acc[i][j] = 0.f;

    for (int c = 0; c < 96; c++) {
        float xv[8], wv[8];
        #pragma unroll
        for (int k = 0; k < 8; k++) xv[k] = Xs[c * 128 + tx + 16 * k];
        #pragma unroll
        for (int jj = 0; jj < 8; jj++) wv[jj] = Ws[c * 65 + ty * 8 + jj];
        #pragma unroll
        for (int jj = 0; jj < 8; jj++)
            #pragma unroll
            for (int k = 0; k < 8; k++) acc[jj][k] = fmaf(wv[jj], xv[k], acc[jj][k]);
    }

    if (j0 < DIQ) {  // xm half -> (B,192,L)
        #pragma unroll
        for (int jj = 0; jj < 8; jj++) {
            float* dst = g_xmt + ((size_t)b * DIQ + j0 + ty * 8 + jj) * LQ + l0 + tx;
            #pragma unroll
            for (int k = 0; k < 8; k++) dst[16 * k] = acc[jj][k];
        }
    } else {         // z half -> silu -> (B,L,192), staged via smem for coalescing
        __syncthreads();
        #pragma unroll
        for (int jj = 0; jj < 8; jj++)
            #pragma unroll
            for (int k = 0; k < 8; k++)
                sm[(tx + 16 * k) * 66 + ty * 8 + jj] = acc[jj][k];
        __syncthreads();
        float* zb = g_zs + ((size_t)b * LQ + l0) * DIQ + (j0 - DIQ);
        for (int idx = tid; idx < 128 * 64; idx += 128) {
            int l = idx >> 6, je = idx & 63;
            zb[(size_t)l * DIQ + je] = siluf(sm[l * 66 + je]);
        }
    }
}

// ---------------- K2: depthwise causal conv (k=4) + silu, with SMEM transpose ----
__global__ __launch_bounds__(256) void mk_conv(const float* __restrict__ cw,
                                               const float* __restrict__ cb) {
    __shared__ float s[32][37];
    const int l0 = blockIdx.x * 32, e0 = blockIdx.y * 32, b = blockIdx.z;
    const int tx = threadIdx.x, ty = threadIdx.y;
    #pragma unroll
    for (int k = 0; k < 4; k++) {
        int e = ty + 8 * k;
        const float* src = g_xmt + ((size_t)b * DIQ + e0 + e) * LQ + l0;
        int l = l0 - 3 + tx;
        s[e][tx] = (l >= 0) ? src[tx - 3] : 0.f;
        if (tx < 3) s[e][tx + 32] = src[tx + 29];
    }
    __syncthreads();
    const float4 w4 = *(const float4*)(cw + (size_t)(e0 + tx) * 4);
    const float bias = cb[e0 + tx];
    float* dst = g_xms + ((size_t)b * LQ + l0) * DIQ + e0 + tx;
    #pragma unroll
    for (int k = 0; k < 4; k++) {
        int ll = ty + 8 * k;
        float v = bias + w4.x * s[tx][ll] + w4.y * s[tx][ll + 1]
                       + w4.z * s[tx][ll + 2] + w4.w * s[tx][ll + 3];
        dst[(size_t)ll * DIQ] = siluf(v);
    }
}

// ---------------- K3: x_proj + dt_proj + softplus -> delta, B, C ----------------
__global__ __launch_bounds__(128) void mk_xproj(const float* __restrict__ xpw,
                                                const float* __restrict__ dtw,
                                                const float* __restrict__ dtb) {
    extern __shared__ float sm[];
    float* Ws = sm;                   // [40][193]
    float* Xs = Ws + 40 * 193;        // [64][193]
    float* Db = Xs + 64 * 193;        // [64][40]
    float* Dt = Db + 64 * 40;         // [192][6]
    float* Bs = Dt + 192 * 6;         // [192]
    const int l0 = blockIdx.x * 64, b = blockIdx.y, tid = threadIdx.x;

    for (int idx = tid; idx < 40 * 192; idx += 128) {
        int r = idx / 192, e = idx - r * 192;
        Ws[r * 193 + e] = (r < 38) ? xpw[(size_t)r * 192 + e] : 0.f;
    }
    const float* xsrc = g_xms + ((size_t)b * LQ + l0) * DIQ;
    for (int idx = tid; idx < 64 * 192; idx += 128) {
        int l = idx / 192, e = idx - l * 192;
        Xs[l * 193 + e] = xsrc[idx];
    }
    for (int idx = tid; idx < 192 * 6; idx += 128) Dt[idx] = dtw[idx];
    for (int idx = tid; idx < 192; idx += 128)     Bs[idx] = dtb[idx];
    __syncthreads();

    // step 1: dbl[l, r<40] = xms . x_proj_w^T  (4l x 5r per thread)
    const int lg = tid & 15, rg = tid >> 4;
    float acc[4][5];
    #pragma unroll
    for (int i = 0; i < 4; i++)
        #pragma unroll
        for (int q = 0; q < 5; q++) acc[i][q] = 0.f;
    for (int e = 0; e < 192; e++) {
        float xv[4], wv[5];
        #pragma unroll
        for (int i = 0; i < 4; i++) xv[i] = Xs[(lg * 4 + i) * 193 + e];
        #pragma unroll
        for (int q = 0; q < 5; q++) wv[q] = Ws[(rg * 5 + q) * 193 + e];
        #pragma unroll
        for (int i = 0; i < 4; i++)
            #pragma unroll
            for (int q = 0; q < 5; q++) acc[i][q] = fmaf(xv[i], wv[q], acc[i][q]);
    }
    #pragma unroll
    for (int i = 0; i < 4; i++)
        #pragma unroll
        for (int q = 0; q < 5; q++) Db[(lg * 4 + i) * 40 + rg * 5 + q] = acc[i][q];
    __syncthreads();

    // step 2: delta = softplus(dt @ dt_proj_w^T + b)
    float* dd = g_delta + ((size_t)b * LQ + l0) * DIQ;
    for (int idx = tid; idx < 64 * 192; idx += 128) {
        int l = idx / 192, e = idx - l * 192;
        float d = Bs[e];
        #pragma unroll
        for (int r = 0; r < 6; r++) d = fmaf(Db[l * 40 + r], Dt[e * 6 + r], d);
        dd[idx] = (d > 15.f) ? d : log1pf(expf(d));
    }
    // step 3: B, C
    float* bb = g_Bm + ((size_t)b * LQ + l0) * DSQ;
    float* cc = g_Cm + ((size_t)b * LQ + l0) * DSQ;
    for (int idx = tid; idx < 64 * 32; idx += 128) {
        int l = idx >> 5, n = idx & 31;
        float v = Db[l * 40 + 6 + n];
        if (n < 16) bb[(size_t)l * DSQ + n] = v;
        else        cc[(size_t)l * DSQ + (n - 16)] = v;
    }
}

// ---------------- K4: scan pass 1 (chunk-local states + sum(delta)) ----------------
__global__ __launch_bounds__(192) void mk_scan1(const float* __restrict__ alog) {
    const int ch = blockIdx.x, b = blockIdx.y, e = threadIdx.x;
    float a[DSQ];
    const bool pat = apat(alog, e, a);
    const float A0 = a[0];
    float h[DSQ];
    #pragma unroll
    for (int n = 0; n < DSQ; n++) h[n] = 0.f;
    float dsum = 0.f;
    const size_t off = (size_t)b * LQ + (size_t)ch * SCHQ;
    const float* dp = g_delta + off * DIQ + e;
    const float* up = g_xms  + off * DIQ + e;
    const float4* bp = reinterpret_cast<const float4*>(g_Bm) + off * 4;

    if (pat) {
        for (int s = 0; s < SCHQ; s++) {
            float delta = dp[(size_t)s * DIQ];
            float u     = up[(size_t)s * DIQ];
            float4 q0 = bp[s * 4], q1 = bp[s * 4 + 1], q2 = bp[s * 4 + 2], q3 = bp[s * 4 + 3];
            float Bv[16] = {q0.x,q0.y,q0.z,q0.w, q1.x,q1.y,q1.z,q1.w,
                            q2.x,q2.y,q2.z,q2.w, q3.x,q3.y,q3.z,q3.w};
            float du = delta * u;
            dsum += delta;
            float pw[16]; pw16f(expf(delta * A0), pw);
            #pragma unroll
            for (int n = 0; n < 16; n++) h[n] = fmaf(pw[n], h[n], du * Bv[n]);
        }
    } else {
        for (int s = 0; s < SCHQ; s++) {
            float delta = dp[(size_t)s * DIQ];
            float u     = up[(size_t)s * DIQ];
            float4 q0 = bp[s * 4], q1 = bp[s * 4 + 1], q2 = bp[s * 4 + 2], q3 = bp[s * 4 + 3];
            float Bv[16] = {q0.x,q0.y,q0.z,q0.w, q1.x,q1.y,q1.z,q1.w,
                            q2.x,q2.y,q2.z,q2.w, q3.x,q3.y,q3.z,q3.w};
            float du = delta * u;
            dsum += delta;
            #pragma unroll
            for (int n = 0; n < 16; n++) h[n] = fmaf(expf(delta * a[n]), h[n], du * Bv[n]);
        }
    }
    float* hd = g_hend + (((size_t)b * NCQ + ch) * DIQ + e) * DSQ;
    #pragma unroll
    for (int n = 0; n < 16; n++) hd[n] = h[n];
    g_dsum[((size_t)b * NCQ + ch) * DIQ + e] = dsum;
}

// ---------------- K5: combine chunk boundary states ----------------
__global__ __launch_bounds__(192) void mk_comb(const float* __restrict__ alog) {
    const int b = blockIdx.x, e = threadIdx.x;
    float a[DSQ];
    const bool pat = apat(alog, e, a);
    const float A0 = a[0];
    float h[DSQ];
    #pragma unroll
    for (int n = 0; n < DSQ; n++) h[n] = 0.f;
    for (int ch = 0; ch < NCQ; ch++) {
        size_t base = (((size_t)b * NCQ + ch) * DIQ + e) * DSQ;
        float* hi = g_hin + base;
        const float* hd = g_hend + base;
        #pragma unroll
        for (int n = 0; n < 16; n++) hi[n] = h[n];
        float ds = g_dsum[((size_t)b * NCQ + ch) * DIQ + e];
        if (pat) {
            float pw[16]; pw16f(expf(ds * A0), pw);
            #pragma unroll
            for (int n = 0; n < 16; n++) h[n] = fmaf(pw[n], h[n], hd[n]);
        } else {
            #pragma unroll
            for (int n = 0; n < 16; n++) h[n] = fmaf(expf(ds * a[n]), h[n], hd[n]);
        }
    }
}

// ---------------- K6: scan pass 2 (replay with h_in, emit y*silu(z)) ----------------
__global__ __launch_bounds__(192) void mk_scan2(const float* __restrict__ alog,
                                                const float* __restrict__ Dg) {
    const int ch = blockIdx.x, b = blockIdx.y, e = threadIdx.x;
    float a[DSQ];
    const bool pat = apat(alog, e, a);
    const float A0 = a[0];
    float h[DSQ];
    const float* hi = g_hin + (((size_t)b * NCQ + ch) * DIQ + e) * DSQ;
    #pragma unroll
    for (int n = 0; n < DSQ; n++) h[n] = hi[n];
    const float Dv = Dg[e];
    const size_t off = (size_t)b * LQ + (size_t)ch * SCHQ;
    const float* dp = g_delta + off * DIQ + e;
    const float* up = g_xms  + off * DIQ + e;
    float*       zp = g_zs   + off * DIQ + e;
    const float4* bp = reinterpret_cast<const float4*>(g_Bm) + off * 4;
    const float4* cp = reinterpret_cast<const float4*>(g_Cm) + off * 4;

    if (pat) {
        for (int s = 0; s < SCHQ; s++) {
            float delta = dp[(size_t)s * DIQ];
            float u     = up[(size_t)s * DIQ];
            float4 q0 = bp[s * 4], q1 = bp[s * 4 + 1], q2 = bp[s * 4 + 2], q3 = bp[s * 4 + 3];
            float Bv[16] = {q0.x,q0.y,q0.z,q0.w, q1.x,q1.y,q1.z,q1.w,
                            q2.x,q2.y,q2.z,q2.w, q3.x,q3.y,q3.z,q3.w};
            float4 c0 = cp[s * 4], c1 = cp[s * 4 + 1], c2 = cp[s * 4 + 2], c3 = cp[s * 4 + 3];
            float Cv[16] = {c0.x,c0.y,c0.z,c0.w, c1.x,c1.y,c1.z,c1.w,
                            c2.x,c2.y,c2.z,c2.w, c3.x,c3.y,c3.z,c3.w};
            float du = delta * u;
            float pw[16]; pw16f(expf(delta * A0), pw);
            float y = u * Dv;
            #pragma unroll
            for (int n = 0; n < 16; n++) {
                h[n] = fmaf(pw[n], h[n], du * Bv[n]);
                y = fmaf(h[n], Cv[n], y);
            }
            zp[(size_t)s * DIQ] = y * zp[(size_t)s * DIQ];
        }
    } else {
        for (int s = 0; s < SCHQ; s++) {
            float delta = dp[(size_t)s * DIQ];
            float u     = up[(size_t)s * DIQ];
            float4 q0 = bp[s * 4], q1 = bp[s * 4 + 1], q2 = bp[s * 4 + 2], q3 = bp[s * 4 + 3];
            float Bv[16] = {q0.x,q0.y,q0.z,q0.w, q1.x,q1.y,q1.z,q1.w,
                            q2.x,q2.y,q2.z,q2.w, q3.x,q3.y,q3.z,q3.w};
            float4 c0 = cp[s * 4], c1 = cp[s * 4 + 1], c2 = cp[s * 4 + 2], c3 = cp[s * 4 + 3];
            float Cv[16] = {c0.x,c0.y,c0.z,c0.w, c1.x,c1.y,c1.z,c1.w,
                            c2.x,c2.y,c2.z,c2.w, c3.x,c3.y,c3.z,c3.w};
            float du = delta * u;
            float y = u * Dv;
            #pragma unroll
            for (int n = 0; n < 16; n++) {
                h[n] = fmaf(expf(delta * a[n]), h[n], du * Bv[n]);
                y = fmaf(h[n], Cv[n], y);
            }
            zp[(size_t)s * DIQ] = y * zp[(size_t)s * DIQ];
        }
    }
}

// ---------------- K7: out_proj GEMM + LayerNorm + transpose to (B,C,H,W) -----------
__global__ __launch_bounds__(128) void mk_outln(const float* __restrict__ ow,
                                                const float* __restrict__ gam,
                                                const float* __restrict__ bet,
                                                float* __restrict__ out) {
    extern __shared__ float sm[];
    float* Ws = sm;                   // [96][193]
    float* Ys = Ws + 96 * 193;        // [64][193]
    float* Os = Ys + 64 * 193;        // [64][97]
    float* Mu = Os + 64 * 97;         // [64]
    float* Rs = Mu + 64;              // [64]
    const int l0 = blockIdx.x * 64, b = blockIdx.y, tid = threadIdx.x;

    for (int idx = tid; idx < 96 * 192; idx += 128) {
        int o = idx / 192, e = idx - o * 192;
        Ws[o * 193 + e] = ow[idx];
    }
    const float* ysrc = g_zs + ((size_t)b * LQ + l0) * DIQ;
    for (int idx = tid; idx < 64 * 192; idx += 128) {
        int l = idx / 192, e = idx - l * 192;
        Ys[l * 193 + e] = ysrc[idx];
    }
    __syncthreads();

    const int lg = tid & 7, og = tid >> 3;   // 8 x 8l, 16 x 6o
    float acc[8][6];
    #pragma unroll
    for (int i = 0; i < 8; i++)
        #pragma unroll
        for (int q = 0; q < 6; q++) acc[i][q] = 0.f;
    for (int e = 0; e < 192; e++) {
        float yv[8], wv[6];
        #pragma unroll
        for (int i = 0; i < 8; i++) yv[i] = Ys[(lg * 8 + i) * 193 + e];
        #pragma unroll
        for (int q = 0; q < 6; q++) wv[q] = Ws[(og * 6 + q) * 193 + e];
        #pragma unroll
        for (int i = 0; i < 8; i++)
            #pragma unroll
            for (int q = 0; q < 6; q++) acc[i][q] = fmaf(yv[i], wv[q], acc[i][q]);
    }
    #pragma unroll
    for (int i = 0; i < 8; i++)
        #pragma unroll
        for (int q = 0; q < 6; q++) Os[(lg * 8 + i) * 97 + og * 6 + q] = acc[i][q];
    __syncthreads();

    if (tid < 64) {
        float s = 0.f;
        for (int o = 0; o < 96; o++) s += Os[tid * 97 + o];
        float mu = s * (1.f / 96.f);
        float v = 0.f;
        for (int o = 0; o < 96; o++) { float d = Os[tid * 97 + o] - mu; v = fmaf(d, d, v); }
        Mu[tid] = mu;
        Rs[tid] = rsqrtf(v * (1.f / 96.f) + 1e-5f);
    }
    __syncthreads();

    float* ob = out + (size_t)b * CQ * LQ + l0;
    for (int idx = tid; idx < 96 * 64; idx += 128) {
        int l = idx & 63, o = idx >> 6;
        ob[(size_t)o * LQ + l] = (Os[l * 97 + o] - Mu[l]) * Rs[l] * gam[o] + bet[o];
    }
}

// ---------------- launch ----------------
extern "C" void kernel_launch(void* const* d_in, const int* in_sizes, int n_in,
                              void* d_out, int out_size) {
    const float* x    = (const float*)d_in[0];
    const float* inw  = (const float*)d_in[1];
    const float* cw   = (const float*)d_in[2];
    const float* cb   = (const float*)d_in[3];
    const float* xpw  = (const float*)d_in[4];
    const float* dtw  = (const float*)d_in[5];
    const float* dtb  = (const float*)d_in[6];
    const float* alog = (const float*)d_in[7];
    const float* Dg   = (const float*)d_in[8];
    const float* ow   = (const float*)d_in[9];
    const float* gam  = (const float*)d_in[10];
    const float* bet  = (const float*)d_in[11];
    float* out = (float*)d_out;

    const int SMEM1 = (96 * 128 + 96 * 65) * 4;                                   // 74112
    const int SMEM3 = (40 * 193 + 64 * 193 + 64 * 40 + 192 * 6 + 192) * 4;        // 95904
    const int SMEM7 = (96 * 193 + 64 * 193 + 64 * 97 + 64 + 64) * 4;              // 148864

    cudaFuncSetAttribute(mk_inproj, cudaFuncAttributeMaxDynamicSharedMemorySize, SMEM1);
    cudaFuncSetAttribute(mk_xproj,  cudaFuncAttributeMaxDynamicSharedMemorySize, SMEM3);
    cudaFuncSetAttribute(mk_outln,  cudaFuncAttributeMaxDynamicSharedMemorySize, SMEM7);

    mk_inproj<<<dim3(LQ / 128, DI2Q / 64, BQ), 128, SMEM1>>>(x, inw);
    mk_conv  <<<dim3(LQ / 32, DIQ / 32, BQ), dim3(32, 8)>>>(cw, cb);
    mk_xproj <<<dim3(LQ / 64, BQ), 128, SMEM3>>>(xpw, dtw, dtb);
    mk_scan1 <<<dim3(NCQ, BQ), DIQ>>>(alog);
    mk_comb  <<<BQ, DIQ>>>(alog);
    mk_scan2 <<<dim3(NCQ, BQ), DIQ>>>(alog, Dg);
    mk_outln <<<dim3(LQ / 64, BQ), 128, SMEM7>>>(ow, gam, bet, out);
}

// round 2
// speedup vs baseline: 1.1060x; 1.1060x over previous
#include <cuda_runtime.h>
#include <math.h>

#define BQ   8
#define CQ   96
#define LQ   4096
#define DIQ  192
#define DI2Q 384
#define DSQ  16
#define NCQ  128
#define SCHQ 32

// ---------------- scratch ----------------
static __device__ float g_xmt [(size_t)BQ * DIQ * LQ];   // xm transposed (B,192,L)
static __device__ float g_zs  [(size_t)BQ * LQ * DIQ];   // silu(z), later y*silu(z)   (B,L,192)
static __device__ float g_xms [(size_t)BQ * LQ * DIQ];   // silu(conv(xm))             (B,L,192)
static __device__ float g_delta[(size_t)BQ * LQ * DIQ];  // softplus(...)              (B,L,192)
static __device__ float g_Bm  [(size_t)BQ * LQ * DSQ];
static __device__ float g_Cm  [(size_t)BQ * LQ * DSQ];
static __device__ float g_hend[(size_t)BQ * NCQ * DIQ * DSQ];
static __device__ float g_hin [(size_t)BQ * NCQ * DIQ * DSQ];
static __device__ float g_dsum[(size_t)BQ * NCQ * DIQ];

// ---------------- helpers ----------------
__device__ __forceinline__ unsigned f2tf(float f) {
    unsigned r; asm("cvt.rna.tf32.f32 %0, %1;" : "=r"(r) : "f"(f)); return r;
}

__device__ __forceinline__ void mma_tf32(float& c0, float& c1, float& c2, float& c3,
                                         unsigned a0, unsigned a1, unsigned a2, unsigned a3,
                                         unsigned b0, unsigned b1) {
    asm("mma.sync.aligned.m16n8k8.row.col.f32.tf32.tf32.f32 "
        "{%0,%1,%2,%3},{%4,%5,%6,%7},{%8,%9},{%0,%1,%2,%3};"
        : "+f"(c0), "+f"(c1), "+f"(c2), "+f"(c3)
        : "r"(a0), "r"(a1), "r"(a2), "r"(a3), "r"(b0), "r"(b1));
}

__device__ __forceinline__ void pw16f(float p1, float* pw) {
    float p2 = p1 * p1, p4 = p2 * p2, p8 = p4 * p4;
    pw[0] = p1;        pw[1] = p2;        pw[2] = p2 * p1;   pw[3] = p4;
    pw[4] = p4 * p1;   pw[5] = p4 * p2;   pw[6] = p4 * pw[2];pw[7] = p8;
    pw[8] = p8 * p1;   pw[9] = p8 * p2;   pw[10]= p8 * pw[2];pw[11]= p8 * p4;
    pw[12]= p8 * pw[4];pw[13]= p8 * pw[5];pw[14]= p8 * pw[6];pw[15]= p8 * p8;
}

__device__ __forceinline__ bool apat(const float* __restrict__ alog, int e, float* a) {
    #pragma unroll
    for (int n = 0; n < DSQ; n++) a[n] = -expf(alog[e * DSQ + n]);
    bool pat = true;
    #pragma unroll
    for (int n = 1; n < DSQ; n++) {
        float tgt = (float)(n + 1) * a[0];
        pat = pat && (fabsf(a[n] - tgt) <= 1e-4f * (1.f + fabsf(tgt)));
    }
    return pat;
}

__device__ __forceinline__ float siluf(float v) { return v / (1.f + expf(-v)); }

// ================ K1: in_proj GEMM (tf32 mma) + split ================
// xz[b,l,j] = sum_c x[b,c,l] * W[j,c]. Block tile 128(l) x 64(j), K=96.
#define K1_AS 136   // As[c(96)][l(128)] stride (==8 mod 32)
#define K1_WS 100   // Ws[j(64)][c(96)] stride (==4 mod 32)
__global__ __launch_bounds__(256) void mk_inproj(const float* __restrict__ x,
                                                 const float* __restrict__ w) {
    extern __shared__ unsigned sm_u[];
    unsigned* As = sm_u;
    unsigned* Ws = sm_u + 96 * K1_AS;
    const int l0 = blockIdx.x * 128, j0 = blockIdx.y * 64, b = blockIdx.z;
    const int tid = threadIdx.x;

    const float* xb = x + (size_t)b * CQ * LQ + l0;
    for (int idx = tid; idx < 96 * 128; idx += 256) {
        int c = idx >> 7, l = idx & 127;
        As[c * K1_AS + l] = f2tf(xb[(size_t)c * LQ + l]);
    }
    for (int idx = tid; idx < 64 * 96; idx += 256) {
        int j = idx / 96, c = idx - j * 96;
        Ws[j * K1_WS + c] = f2tf(w[(size_t)(j0 + j) * 96 + c]);
    }
    __syncthreads();

    const int warp = tid >> 5, lane = tid & 31, g = lane >> 2, tg = lane & 3;
    const int wm = (warp & 3) * 32, wn = (warp >> 2) * 32;

    float acc[2][4][4];
    #pragma unroll
    for (int i = 0; i < 2; i++)
        #pragma unroll
        for (int jf = 0; jf < 4; jf++)
            #pragma unroll
            for (int q = 0; q < 4; q++) acc[i][jf][q] = 0.f;

    #pragma unroll
    for (int ks = 0; ks < 12; ks++) {
        int k0 = ks * 8;
        unsigned a[2][4];
        #pragma unroll
        for (int i = 0; i < 2; i++) {
            int m = wm + i * 16;
            a[i][0] = As[(k0 + tg) * K1_AS + m + g];
            a[i][1] = As[(k0 + tg) * K1_AS + m + g + 8];
            a[i][2] = As[(k0 + tg + 4) * K1_AS + m + g];
            a[i][3] = As[(k0 + tg + 4) * K1_AS + m + g + 8];
        }
        #pragma unroll
        for (int jf = 0; jf < 4; jf++) {
            int n = wn + jf * 8 + g;
            unsigned b0 = Ws[n * K1_WS + k0 + tg];
            unsigned b1 = Ws[n * K1_WS + k0 + tg + 4];
            #pragma unroll
            for (int i = 0; i < 2; i++)
                mma_tf32(acc[i][jf][0], acc[i][jf][1], acc[i][jf][2], acc[i][jf][3],
                         a[i][0], a[i][1], a[i][2], a[i][3], b0, b1);
        }
    }
    __syncthreads();
    float* Os = (float*)sm_u;

    if (j0 < DIQ) {
        // Os[n(64)][m(128)] stride K1_AS, then coalesced write to g_xmt
        #pragma unroll
        for (int i = 0; i < 2; i++)
            #pragma unroll
            for (int jf = 0; jf < 4; jf++) {
                int m = wm + i * 16 + g, n = wn + jf * 8 + tg * 2;
                Os[n * K1_AS + m]           = acc[i][jf][0];
                Os[(n + 1) * K1_AS + m]     = acc[i][jf][1];
                Os[n * K1_AS + m + 8]       = acc[i][jf][2];
                Os[(n + 1) * K1_AS + m + 8] = acc[i][jf][3];
            }
        __syncthreads();
        for (int idx = tid; idx < 64 * 128; idx += 256) {
            int n = idx >> 7, m = idx & 127;
            g_xmt[((size_t)b * DIQ + j0 + n) * LQ + l0 + m] = Os[n * K1_AS + m];
        }
    } else {
        // Os[m(128)][n(64)] stride 68, then silu + coalesced write to g_zs
        #pragma unroll
        for (int i = 0; i < 2; i++)
            #pragma unroll
            for (int jf = 0; jf < 4; jf++) {
                int m = wm + i * 16 + g, n = wn + jf * 8 + tg * 2;
                Os[m * 68 + n]           = acc[i][jf][0];
                Os[m * 68 + n + 1]       = acc[i][jf][1];
                Os[(m + 8) * 68 + n]     = acc[i][jf][2];
                Os[(m + 8) * 68 + n + 1] = acc[i][jf][3];
            }
        __syncthreads();
        for (int idx = tid; idx < 128 * 64; idx += 256) {
            int l = idx >> 6, n = idx & 63;
            g_zs[((size_t)b * LQ + l0 + l) * DIQ + (j0 - DIQ) + n] = siluf(Os[l * 68 + n]);
        }
    }
}

// ================ K2: depthwise causal conv + silu ================
__global__ __launch_bounds__(256) void mk_conv(const float* __restrict__ cw,
                                               const float* __restrict__ cb) {
    __shared__ float s[32][37];
    const int l0 = blockIdx.x * 32, e0 = blockIdx.y * 32, b = blockIdx.z;
    const int tx = threadIdx.x, ty = threadIdx.y;
    #pragma unroll
    for (int k = 0; k < 4; k++) {
        int e = ty + 8 * k;
        const float* src = g_xmt + ((size_t)b * DIQ + e0 + e) * LQ + l0;
        int l = l0 - 3 + tx;
        s[e][tx] = (l >= 0) ? src[tx - 3] : 0.f;
        if (tx < 3) s[e][tx + 32] = src[tx + 29];
    }
    __syncthreads();
    const float4 w4 = *(const float4*)(cw + (size_t)(e0 + tx) * 4);
    const float bias = cb[e0 + tx];
    float* dst = g_xms + ((size_t)b * LQ + l0) * DIQ + e0 + tx;
    #pragma unroll
    for (int k = 0; k < 4; k++) {
        int ll = ty + 8 * k;
        float v = bias + w4.x * s[tx][ll] + w4.y * s[tx][ll + 1]
                       + w4.z * s[tx][ll + 2] + w4.w * s[tx][ll + 3];
        dst[(size_t)ll * DIQ] = siluf(v);
    }
}

// ================ K3: x_proj (tf32 mma) + dt_proj + softplus ================
// dbl[l, r<40] = xms . x_proj_w^T (rows 38,39 zero-padded). Block tile 128(l) x 40(r), K=192.
#define K3_AS 68    // As[l(128)][e(64)] stride (==4 mod 32)
#define K3_WS 68    // Ws[r(40)][e(64)] stride
__global__ __launch_bounds__(256) void mk_xproj(const float* __restrict__ xpw,
                                                const float* __restrict__ dtw,
                                                const float* __restrict__ dtb) {
    extern __shared__ unsigned sm_u[];
    unsigned* As = sm_u;                       // [128][68]
    unsigned* Ws = sm_u + 128 * K3_AS;         // [40][68]
    float*    Db = (float*)(Ws + 40 * K3_WS);  // [128][40]
    float*    Dt = Db + 128 * 40;              // [192][6]
    float*    Bs = Dt + 192 * 6;               // [192]
    const int l0 = blockIdx.x * 128, b = blockIdx.y, tid = threadIdx.x;

    for (int idx = tid; idx < 192 * 6; idx += 256) Dt[idx] = dtw[idx];
    for (int idx = tid; idx < 192; idx += 256)     Bs[idx] = dtb[idx];

    const int warp = tid >> 5, lane = tid & 31, g = lane >> 2, tg = lane & 3;
    const int wm = warp * 16;   // 8 warps cover 128 rows

    float acc[5][4];
    #pragma unroll
    for (int jf = 0; jf < 5; jf++)
        #pragma unroll
        for (int q = 0; q < 4; q++) acc[jf][q] = 0.f;

    const float* xsrc = g_xms + ((size_t)b * LQ + l0) * DIQ;
    for (int kc = 0; kc < 3; kc++) {
        int e0 = kc * 64;
        __syncthreads();
        for (int idx = tid; idx < 128 * 64; idx += 256) {
            int l = idx >> 6, e = idx & 63;
            As[l * K3_AS + e] = f2tf(xsrc[(size_t)l * DIQ + e0 + e]);
        }
        for (int idx = tid; idx < 40 * 64; idx += 256) {
            int r = idx >> 6, e = idx & 63;
            Ws[r * K3_WS + e] = (r < 38) ? f2tf(xpw[(size_t)r * DIQ + e0 + e]) : 0u;
        }
        __syncthreads();
        #pragma unroll
        for (int ks = 0; ks < 8; ks++) {
            int k0 = ks * 8;
            unsigned a0 = As[(wm + g) * K3_AS + k0 + tg];
            unsigned a1 = As[(wm + g + 8) * K3_AS + k0 + tg];
            unsigned a2 = As[(wm + g) * K3_AS + k0 + tg + 4];
            unsigned a3 = As[(wm + g + 8) * K3_AS + k0 + tg + 4];
            #pragma unroll
            for (int jf = 0; jf < 5; jf++) {
                int n = jf * 8 + g;
                unsigned b0 = Ws[n * K3_WS + k0 + tg];
                unsigned b1 = Ws[n * K3_WS + k0 + tg + 4];
                mma_tf32(acc[jf][0], acc[jf][1], acc[jf][2], acc[jf][3],
                         a0, a1, a2, a3, b0, b1);
            }
        }
    }
    __syncthreads();
    #pragma unroll
    for (int jf = 0; jf < 5; jf++) {
        int m = wm + g, n = jf * 8 + tg * 2;
        Db[m * 40 + n]           = acc[jf][0];
        Db[m * 40 + n + 1]       = acc[jf][1];
        Db[(m + 8) * 40 + n]     = acc[jf][2];
        Db[(m + 8) * 40 + n + 1] = acc[jf][3];
    }
    __syncthreads();

    // delta = softplus(dt @ dt_proj_w^T + b)
    float* dd = g_delta + ((size_t)b * LQ + l0) * DIQ;
    for (int idx = tid; idx < 128 * 192; idx += 256) {
        int l = idx / 192, e = idx - l * 192;
        float d = Bs[e];
        #pragma unroll
        for (int r = 0; r < 6; r++) d = fmaf(Db[l * 40 + r], Dt[e * 6 + r], d);
        dd[idx] = (d > 15.f) ? d : log1pf(expf(d));
    }
    // B, C
    float* bb = g_Bm + ((size_t)b * LQ + l0) * DSQ;
    float* cc = g_Cm + ((size_t)b * LQ + l0) * DSQ;
    for (int idx = tid; idx < 128 * 32; idx += 256) {
        int l = idx >> 5, n = idx & 31;
        float v = Db[l * 40 + 6 + n];
        if (n < 16) bb[(size_t)l * DSQ + n] = v;
        else        cc[(size_t)l * DSQ + (n - 16)] = v;
    }
}

// ================ K4: scan pass 1 ================
__global__ __launch_bounds__(192) void mk_scan1(const float* __restrict__ alog) {
    const int ch = blockIdx.x, b = blockIdx.y, e = threadIdx.x;
    float a[DSQ];
    const bool pat = apat(alog, e, a);
    const float A0 = a[0];
    float h[DSQ];
    #pragma unroll
    for (int n = 0; n < DSQ; n++) h[n] = 0.f;
    float dsum = 0.f;
    const size_t off = (size_t)b * LQ + (size_t)ch * SCHQ;
    const float* dp = g_delta + off * DIQ + e;
    const float* up = g_xms  + off * DIQ + e;
    const float4* bp = reinterpret_cast<const float4*>(g_Bm) + off * 4;

    if (pat) {
        #pragma unroll 4
        for (int s = 0; s < SCHQ; s++) {
            float delta = dp[(size_t)s * DIQ];
            float u     = up[(size_t)s * DIQ];
            float4 q0 = bp[s * 4], q1 = bp[s * 4 + 1], q2 = bp[s * 4 + 2], q3 = bp[s * 4 + 3];
            float Bv[16] = {q0.x,q0.y,q0.z,q0.w, q1.x,q1.y,q1.z,q1.w,
                            q2.x,q2.y,q2.z,q2.w, q3.x,q3.y,q3.z,q3.w};
            float du = delta * u;
            dsum += delta;
            float pw[16]; pw16f(expf(delta * A0), pw);
            #pragma unroll
            for (int n = 0; n < 16; n++) h[n] = fmaf(pw[n], h[n], du * Bv[n]);
        }
    } else {
        #pragma unroll 2
        for (int s = 0; s < SCHQ; s++) {
            float delta = dp[(size_t)s * DIQ];
            float u     = up[(size_t)s * DIQ];
            float4 q0 = bp[s * 4], q1 = bp[s * 4 + 1], q2 = bp[s * 4 + 2], q3 = bp[s * 4 + 3];
            float Bv[16] = {q0.x,q0.y,q0.z,q0.w, q1.x,q1.y,q1.z,q1.w,
                            q2.x,q2.y,q2.z,q2.w, q3.x,q3.y,q3.z,q3.w};
            float du = delta * u;
            dsum += delta;
            #pragma unroll
            for (int n = 0; n < 16; n++) h[n] = fmaf(expf(delta * a[n]), h[n], du * Bv[n]);
        }
    }
    float* hd = g_hend + (((size_t)b * NCQ + ch) * DIQ + e) * DSQ;
    #pragma unroll
    for (int n = 0; n < 16; n++) hd[n] = h[n];
    g_dsum[((size_t)b * NCQ + ch) * DIQ + e] = dsum;
}

// ================ K5: combine chunk boundary states ================
__global__ __launch_bounds__(192) void mk_comb(const float* __restrict__ alog) {
    const int b = blockIdx.x, e = threadIdx.x;
    float a[DSQ];
    const bool pat = apat(alog, e, a);
    const float A0 = a[0];
    float h[DSQ];
    #pragma unroll
    for (int n = 0; n < DSQ; n++) h[n] = 0.f;
    #pragma unroll 4
    for (int ch = 0; ch < NCQ; ch++) {
        size_t base = (((size_t)b * NCQ + ch) * DIQ + e) * DSQ;
        float* hi = g_hin + base;
        const float* hd = g_hend + base;
        #pragma unroll
        for (int n = 0; n < 16; n++) hi[n] = h[n];
        float ds = g_dsum[((size_t)b * NCQ + ch) * DIQ + e];
        if (pat) {
            float pw[16]; pw16f(expf(ds * A0), pw);
            #pragma unroll
            for (int n = 0; n < 16; n++) h[n] = fmaf(pw[n], h[n], hd[n]);
        } else {
            #pragma unroll
            for (int n = 0; n < 16; n++) h[n] = fmaf(expf(ds * a[n]), h[n], hd[n]);
        }
    }
}

// ================ K6: scan pass 2 ================
__global__ __launch_bounds__(192) void mk_scan2(const float* __restrict__ alog,
                                                const float* __restrict__ Dg) {
    const int ch = blockIdx.x, b = blockIdx.y, e = threadIdx.x;
    float a[DSQ];
    const bool pat = apat(alog, e, a);
    const float A0 = a[0];
    float h[DSQ];
    const float* hi = g_hin + (((size_t)b * NCQ + ch) * DIQ + e) * DSQ;
    #pragma unroll
    for (int n = 0; n < DSQ; n++) h[n] = hi[n];
    const float Dv = Dg[e];
    const size_t off = (size_t)b * LQ + (size_t)ch * SCHQ;
    const float* dp = g_delta + off * DIQ + e;
    const float* up = g_xms  + off * DIQ + e;
    float*       zp = g_zs   + off * DIQ + e;
    const float4* bp = reinterpret_cast<const float4*>(g_Bm) + off * 4;
    const float4* cp = reinterpret_cast<const float4*>(g_Cm) + off * 4;

    if (pat) {
        #pragma unroll 2
        for (int s = 0; s < SCHQ; s++) {
            float delta = dp[(size_t)s * DIQ];
            float u     = up[(size_t)s * DIQ];
            float4 q0 = bp[s * 4], q1 = bp[s * 4 + 1], q2 = bp[s * 4 + 2], q3 = bp[s * 4 + 3];
            float Bv[16] = {q0.x,q0.y,q0.z,q0.w, q1.x,q1.y,q1.z,q1.w,
                            q2.x,q2.y,q2.z,q2.w, q3.x,q3.y,q3.z,q3.w};
            float4 c0 = cp[s * 4], c1 = cp[s * 4 + 1], c2 = cp[s * 4 + 2], c3 = cp[s * 4 + 3];
            float Cv[16] = {c0.x,c0.y,c0.z,c0.w, c1.x,c1.y,c1.z,c1.w,
                            c2.x,c2.y,c2.z,c2.w, c3.x,c3.y,c3.z,c3.w};
            float du = delta * u;
            float pw[16]; pw16f(expf(delta * A0), pw);
            float y = u * Dv;
            #pragma unroll
            for (int n = 0; n < 16; n++) {
                h[n] = fmaf(pw[n], h[n], du * Bv[n]);
                y = fmaf(h[n], Cv[n], y);
            }
            zp[(size_t)s * DIQ] = y * zp[(size_t)s * DIQ];
        }
    } else {
        for (int s = 0; s < SCHQ; s++) {
            float delta = dp[(size_t)s * DIQ];
            float u     = up[(size_t)s * DIQ];
            float4 q0 = bp[s * 4], q1 = bp[s * 4 + 1], q2 = bp[s * 4 + 2], q3 = bp[s * 4 + 3];
            float Bv[16] = {q0.x,q0.y,q0.z,q0.w, q1.x,q1.y,q1.z,q1.w,
                            q2.x,q2.y,q2.z,q2.w, q3.x,q3.y,q3.z,q3.w};
            float4 c0 = cp[s * 4], c1 = cp[s * 4 + 1], c2 = cp[s * 4 + 2], c3 = cp[s * 4 + 3];
            float Cv[16] = {c0.x,c0.y,c0.z,c0.w, c1.x,c1.y,c1.z,c1.w,
                            c2.x,c2.y,c2.z,c2.w, c3.x,c3.y,c3.z,c3.w};
            float du = delta * u;
            float y = u * Dv;
            #pragma unroll
            for (int n = 0; n < 16; n++) {
                h[n] = fmaf(expf(delta * a[n]), h[n], du * Bv[n]);
                y = fmaf(h[n], Cv[n], y);
            }
            zp[(size_t)s * DIQ] = y * zp[(size_t)s * DIQ];
        }
    }
}

// ================ K7: out_proj (tf32 mma) + LayerNorm + transpose ================
// out[b,l,o] = sum_e yz[b,l,e] * W[o,e]. Block tile 128(l) x 96(o), K=192 (3 chunks).
#define K7_AS 68    // As[l(128)][e(64)]
#define K7_WS 68    // Ws[o(96)][e(64)]
__global__ __launch_bounds__(256) void mk_outln(const float* __restrict__ ow,
                                                const float* __restrict__ gam,
                                                const float* __restrict__ bet,
                                                float* __restrict__ out) {
    extern __shared__ unsigned sm_u[];
    unsigned* As = sm_u;                        // [128][68]
    unsigned* Ws = sm_u + 128 * K7_AS;          // [96][68]
    float* Os = (float*)sm_u;                   // [128][100] (reuse after mma)
    float* Mu = (float*)(sm_u + 128 * K7_AS + 96 * K7_WS);         // [128]
    float* Rs = Mu + 128;                                          // [128]
    const int l0 = blockIdx.x * 128, b = blockIdx.y, tid = threadIdx.x;

    const int warp = tid >> 5, lane = tid & 31, g = lane >> 2, tg = lane & 3;
    const int wm = (warp & 3) * 32, wn = (warp >> 2) * 48;

    float acc[2][6][4];
    #pragma unroll
    for (int i = 0; i < 2; i++)
        #pragma unroll
        for (int jf = 0; jf < 6; jf++)
            #pragma unroll
            for (int q = 0; q < 4; q++) acc[i][jf][q] = 0.f;

    const float* ysrc = g_zs + ((size_t)b * LQ + l0) * DIQ;
    for (int kc = 0; kc < 3; kc++) {
        int e0 = kc * 64;
        __syncthreads();
        for (int idx = tid; idx < 128 * 64; idx += 256) {
            int l = idx >> 6, e = idx & 63;
            As[l * K7_AS + e] = f2tf(ysrc[(size_t)l * DIQ + e0 + e]);
        }
        for (int idx = tid; idx < 96 * 64; idx += 256) {
            int o = idx >> 6, e = idx & 63;
            Ws[o * K7_WS + e] = f2tf(ow[(size_t)o * DIQ + e0 + e]);
        }
        __syncthreads();
        #pragma unroll
        for (int ks = 0; ks < 8; ks++) {
            int k0 = ks * 8;
            unsigned a[2][4];
            #pragma unroll
            for (int i = 0; i < 2; i++) {
                int m = wm + i * 16;
                a[i][0] = As[(m + g) * K7_AS + k0 + tg];
                a[i][1] = As[(m + g + 8) * K7_AS + k0 + tg];
                a[i][2] = As[(m + g) * K7_AS + k0 + tg + 4];
                a[i][3] = As[(m + g + 8) * K7_AS + k0 + tg + 4];
            }
            #pragma unroll
            for (int jf = 0; jf < 6; jf++) {
                int n = wn + jf * 8 + g;
                unsigned b0 = Ws[n * K7_WS + k0 + tg];
                unsigned b1 = Ws[n * K7_WS + k0 + tg + 4];
                #pragma unroll
                for (int i = 0; i < 2; i++)
                    mma_tf32(acc[i][jf][0], acc[i][jf][1], acc[i][jf][2], acc[i][jf][3],
                             a[i][0], a[i][1], a[i][2], a[i][3], b0, b1);
            }
        }
    }
    __syncthreads();
    // Os[l][o] stride 100
    #pragma unroll
    for (int i = 0; i < 2; i++)
        #pragma unroll
        for (int jf = 0; jf < 6; jf++) {
            int m = wm + i * 16 + g, n = wn + jf * 8 + tg * 2;
            Os[m * 100 + n]           = acc[i][jf][0];
            Os[m * 100 + n + 1]       = acc[i][jf][1];
            Os[(m + 8) * 100 + n]     = acc[i][jf][2];
            Os[(m + 8) * 100 + n + 1] = acc[i][jf][3];
        }
    __syncthreads();

    if (tid < 128) {
        float s = 0.f;
        for (int o = 0; o < 96; o++) s += Os[tid * 100 + o];
        float mu = s * (1.f / 96.f);
        float v = 0.f;
        for (int o = 0; o < 96; o++) { float d = Os[tid * 100 + o] - mu; v = fmaf(d, d, v); }
        Mu[tid] = mu;
        Rs[tid] = rsqrtf(v * (1.f / 96.f) + 1e-5f);
    }
    __syncthreads();

    float* ob = out + (size_t)b * CQ * LQ + l0;
    for (int idx = tid; idx < 96 * 128; idx += 256) {
        int o = idx >> 7, l = idx & 127;
        ob[(size_t)o * LQ + l] = (Os[l * 100 + o] - Mu[l]) * Rs[l] * gam[o] + bet[o];
    }
}

// ================ launch ================
extern "C" void kernel_launch(void* const* d_in, const int* in_sizes, int n_in,
                              void* d_out, int out_size) {
    const float* x    = (const float*)d_in[0];
    const float* inw  = (const float*)d_in[1];
    const float* cw   = (const float*)d_in[2];
    const float* cb   = (const float*)d_in[3];
    const float* xpw  = (const float*)d_in[4];
    const float* dtw  = (const float*)d_in[5];
    const float* dtb  = (const float*)d_in[6];
    const float* alog = (const float*)d_in[7];
    const float* Dg   = (const float*)d_in[8];
    const float* ow   = (const float*)d_in[9];
    const float* gam  = (const float*)d_in[10];
    const float* bet  = (const float*)d_in[11];
    float* out = (float*)d_out;

    const int SMEM1 = (96 * K1_AS + 64 * K1_WS) * 4;                              // 77824
    const int SMEM3 = (128 * K3_AS + 40 * K3_WS + 128 * 40 + 192 * 6 + 192) * 4;  // 71552
    const int SMEM7 = (128 * K7_AS + 96 * K7_WS + 256) * 4;                       // 61952

    cudaFuncSetAttribute(mk_inproj, cudaFuncAttributeMaxDynamicSharedMemorySize, SMEM1);
    cudaFuncSetAttribute(mk_xproj,  cudaFuncAttributeMaxDynamicSharedMemorySize, SMEM3);
    cudaFuncSetAttribute(mk_outln,  cudaFuncAttributeMaxDynamicSharedMemorySize, SMEM7);

    mk_inproj<<<dim3(LQ / 128, DI2Q / 64, BQ), 256, SMEM1>>>(x, inw);
    mk_conv  <<<dim3(LQ / 32, DIQ / 32, BQ), dim3(32, 8)>>>(cw, cb);
    mk_xproj <<<dim3(LQ / 128, BQ), 256, SMEM3>>>(xpw, dtw, dtb);
    mk_scan1 <<<dim3(NCQ, BQ), DIQ>>>(alog);
    mk_comb  <<<BQ, DIQ>>>(alog);
    mk_scan2 <<<dim3(NCQ, BQ), DIQ>>>(alog, Dg);
    mk_outln <<<dim3(LQ / 128, BQ), 256, SMEM7>>>(ow, gam, bet, out);
}

// round 3
// speedup vs baseline: 2.0965x; 1.8957x over previous
#include <cuda_runtime.h>
#include <math.h>

#define BQ   8
#define CQ   96
#define LQ   4096
#define DIQ  192
#define DI2Q 384
#define DSQ  16
#define NCQ  128
#define SCHQ 32

// ---------------- scratch ----------------
static __device__ float  g_xmt [(size_t)BQ * DIQ * LQ];    // xm transposed (B,192,L)
static __device__ float  g_zs  [(size_t)BQ * LQ * DIQ];    // silu(z), later y*silu(z)
static __device__ float  g_xms [(size_t)BQ * LQ * DIQ];    // silu(conv(xm))
static __device__ float2 g_pd  [(size_t)BQ * LQ * DIQ];    // (p1=exp(delta*A0), du=delta*u)
static __device__ float  g_Bm  [(size_t)BQ * LQ * DSQ];
static __device__ float  g_Cm  [(size_t)BQ * LQ * DSQ];
static __device__ float  g_hend[(size_t)BQ * NCQ * DIQ * DSQ];
static __device__ float  g_hin [(size_t)BQ * NCQ * DIQ * DSQ];
static __device__ float  g_P   [(size_t)BQ * NCQ * DIQ];

// ---------------- fast math helpers (no libm, no heavy MUFU) ----------------
__device__ __forceinline__ float fexp(float x) {
    float y = fmaf(x, 1.442695041f, 0.f);
    y = fminf(fmaxf(y, -126.f), 127.f);
    float n = rintf(y);
    float f = y - n;
    float p =             1.3388908e-3f;
    p = fmaf(p, f, 9.6732550e-3f);
    p = fmaf(p, f, 5.5504110e-2f);
    p = fmaf(p, f, 2.4022652e-1f);
    p = fmaf(p, f, 6.9314718e-1f);
    p = fmaf(p, f, 1.0f);
    return __int_as_float(__float_as_int(p) + (((int)n) << 23));
}

__device__ __forceinline__ float siluf(float v) {
    return __fdividef(v, 1.f + fexp(-v));
}

__device__ __forceinline__ float softplusf(float d) {
    return (d > 15.f) ? d : __logf(1.f + fexp(d));
}

__device__ __forceinline__ unsigned f2tf(float f) {
    unsigned r; asm("cvt.rna.tf32.f32 %0, %1;" : "=r"(r) : "f"(f)); return r;
}

__device__ __forceinline__ void mma_tf32(float& c0, float& c1, float& c2, float& c3,
                                         unsigned a0, unsigned a1, unsigned a2, unsigned a3,
                                         unsigned b0, unsigned b1) {
    asm("mma.sync.aligned.m16n8k8.row.col.f32.tf32.tf32.f32 "
        "{%0,%1,%2,%3},{%4,%5,%6,%7},{%8,%9},{%0,%1,%2,%3};"
        : "+f"(c0), "+f"(c1), "+f"(c2), "+f"(c3)
        : "r"(a0), "r"(a1), "r"(a2), "r"(a3), "r"(b0), "r"(b1));
}

__device__ __forceinline__ void pw16f(float p1, float* pw) {
    float p2 = p1 * p1, p4 = p2 * p2, p8 = p4 * p4;
    pw[0] = p1;        pw[1] = p2;        pw[2] = p2 * p1;   pw[3] = p4;
    pw[4] = p4 * p1;   pw[5] = p4 * p2;   pw[6] = p4 * pw[2];pw[7] = p8;
    pw[8] = p8 * p1;   pw[9] = p8 * p2;   pw[10]= p8 * pw[2];pw[11]= p8 * p4;
    pw[12]= p8 * pw[4];pw[13]= p8 * pw[5];pw[14]= p8 * pw[6];pw[15]= p8 * p8;
}

__device__ __forceinline__ bool apat(const float* __restrict__ alog, int e, float* a) {
    #pragma unroll
    for (int n = 0; n < DSQ; n++) a[n] = -fexp(alog[e * DSQ + n]);
    bool pat = true;
    #pragma unroll
    for (int n = 1; n < DSQ; n++) {
        float tgt = (float)(n + 1) * a[0];
        pat = pat && (fabsf(a[n] - tgt) <= 1e-4f * (1.f + fabsf(tgt)));
    }
    return pat;
}

// ================ K1: in_proj GEMM (tf32 mma) + split ================
#define K1_AS 136
#define K1_WS 100
__global__ __launch_bounds__(256) void mk_inproj(const float* __restrict__ x,
                                                 const float* __restrict__ w) {
    extern __shared__ unsigned sm_u[];
    unsigned* As = sm_u;
    unsigned* Ws = sm_u + 96 * K1_AS;
    const int l0 = blockIdx.x * 128, j0 = blockIdx.y * 64, b = blockIdx.z;
    const int tid = threadIdx.x;

    const float* xb = x + (size_t)b * CQ * LQ + l0;
    for (int idx = tid; idx < 96 * 128; idx += 256) {
        int c = idx >> 7, l = idx & 127;
        As[c * K1_AS + l] = f2tf(xb[(size_t)c * LQ + l]);
    }
    for (int idx = tid; idx < 64 * 96; idx += 256) {
        int j = idx / 96, c = idx - j * 96;
        Ws[j * K1_WS + c] = f2tf(w[(size_t)(j0 + j) * 96 + c]);
    }
    __syncthreads();

    const int warp = tid >> 5, lane = tid & 31, g = lane >> 2, tg = lane & 3;
    const int wm = (warp & 3) * 32, wn = (warp >> 2) * 32;

    float acc[2][4][4];
    #pragma unroll
    for (int i = 0; i < 2; i++)
        #pragma unroll
        for (int jf = 0; jf < 4; jf++)
            #pragma unroll
            for (int q = 0; q < 4; q++) acc[i][jf][q] = 0.f;

    #pragma unroll
    for (int ks = 0; ks < 12; ks++) {
        int k0 = ks * 8;
        unsigned a[2][4];
        #pragma unroll
        for (int i = 0; i < 2; i++) {
            int m = wm + i * 16;
            a[i][0] = As[(k0 + tg) * K1_AS + m + g];
            a[i][1] = As[(k0 + tg) * K1_AS + m + g + 8];
            a[i][2] = As[(k0 + tg + 4) * K1_AS + m + g];
            a[i][3] = As[(k0 + tg + 4) * K1_AS + m + g + 8];
        }
        #pragma unroll
        for (int jf = 0; jf < 4; jf++) {
            int n = wn + jf * 8 + g;
            unsigned b0 = Ws[n * K1_WS + k0 + tg];
            unsigned b1 = Ws[n * K1_WS + k0 + tg + 4];
            #pragma unroll
            for (int i = 0; i < 2; i++)
                mma_tf32(acc[i][jf][0], acc[i][jf][1], acc[i][jf][2], acc[i][jf][3],
                         a[i][0], a[i][1], a[i][2], a[i][3], b0, b1);
        }
    }
    __syncthreads();
    float* Os = (float*)sm_u;

    if (j0 < DIQ) {
        #pragma unroll
        for (int i = 0; i < 2; i++)
            #pragma unroll
            for (int jf = 0; jf < 4; jf++) {
                int m = wm + i * 16 + g, n = wn + jf * 8 + tg * 2;
                Os[n * K1_AS + m]           = acc[i][jf][0];
                Os[(n + 1) * K1_AS + m]     = acc[i][jf][1];
                Os[n * K1_AS + m + 8]       = acc[i][jf][2];
                Os[(n + 1) * K1_AS + m + 8] = acc[i][jf][3];
            }
        __syncthreads();
        for (int idx = tid; idx < 64 * 128; idx += 256) {
            int n = idx >> 7, m = idx & 127;
            g_xmt[((size_t)b * DIQ + j0 + n) * LQ + l0 + m] = Os[n * K1_AS + m];
        }
    } else {
        #pragma unroll
        for (int i = 0; i < 2; i++)
            #pragma unroll
            for (int jf = 0; jf < 4; jf++) {
                int m = wm + i * 16 + g, n = wn + jf * 8 + tg * 2;
                Os[m * 68 + n]           = acc[i][jf][0];
                Os[m * 68 + n + 1]       = acc[i][jf][1];
                Os[(m + 8) * 68 + n]     = acc[i][jf][2];
                Os[(m + 8) * 68 + n + 1] = acc[i][jf][3];
            }
        __syncthreads();
        for (int idx = tid; idx < 128 * 64; idx += 256) {
            int l = idx >> 6, n = idx & 63;
            g_zs[((size_t)b * LQ + l0 + l) * DIQ + (j0 - DIQ) + n] = siluf(Os[l * 68 + n]);
        }
    }
}

// ================ K2: depthwise causal conv + silu ================
__global__ __launch_bounds__(256) void mk_conv(const float* __restrict__ cw,
                                               const float* __restrict__ cb) {
    __shared__ float s[32][37];
    const int l0 = blockIdx.x * 32, e0 = blockIdx.y * 32, b = blockIdx.z;
    const int tx = threadIdx.x, ty = threadIdx.y;
    #pragma unroll
    for (int k = 0; k < 4; k++) {
        int e = ty + 8 * k;
        const float* src = g_xmt + ((size_t)b * DIQ + e0 + e) * LQ + l0;
        int l = l0 - 3 + tx;
        s[e][tx] = (l >= 0) ? src[tx - 3] : 0.f;
        if (tx < 3) s[e][tx + 32] = src[tx + 29];
    }
    __syncthreads();
    const float4 w4 = *(const float4*)(cw + (size_t)(e0 + tx) * 4);
    const float bias = cb[e0 + tx];
    float* dst = g_xms + ((size_t)b * LQ + l0) * DIQ + e0 + tx;
    #pragma unroll
    for (int k = 0; k < 4; k++) {
        int ll = ty + 8 * k;
        float v = bias + w4.x * s[tx][ll] + w4.y * s[tx][ll + 1]
                       + w4.z * s[tx][ll + 2] + w4.w * s[tx][ll + 3];
        dst[(size_t)ll * DIQ] = siluf(v);
    }
}

// ================ K3: x_proj (tf32 mma) + dt_proj + softplus + (p1, du) ================
#define K3_AS 68
#define K3_WS 68
__global__ __launch_bounds__(256) void mk_xproj(const float* __restrict__ xpw,
                                                const float* __restrict__ dtw,
                                                const float* __restrict__ dtb,
                                                const float* __restrict__ alog) {
    extern __shared__ unsigned sm_u[];
    unsigned* As = sm_u;                       // [128][68]
    unsigned* Ws = sm_u + 128 * K3_AS;         // [40][68]
    float*    Db = (float*)(Ws + 40 * K3_WS);  // [128][40]
    float*    Dt = Db + 128 * 40;              // [192][6]
    float*    Bs = Dt + 192 * 6;               // [192]
    float*    A0s = Bs + 192;                  // [192]
    const int l0 = blockIdx.x * 128, b = blockIdx.y, tid = threadIdx.x;

    for (int idx = tid; idx < 192 * 6; idx += 256) Dt[idx] = dtw[idx];
    if (tid < 192) {
        Bs[tid]  = dtb[tid];
        A0s[tid] = -fexp(alog[tid * DSQ]);
    }

    const int warp = tid >> 5, lane = tid & 31, g = lane >> 2, tg = lane & 3;
    const int wm = warp * 16;

    float acc[5][4];
    #pragma unroll
    for (int jf = 0; jf < 5; jf++)
        #pragma unroll
        for (int q = 0; q < 4; q++) acc[jf][q] = 0.f;

    const float* xsrc = g_xms + ((size_t)b * LQ + l0) * DIQ;
    for (int kc = 0; kc < 3; kc++) {
        int e0 = kc * 64;
        __syncthreads();
        for (int idx = tid; idx < 128 * 64; idx += 256) {
            int l = idx >> 6, e = idx & 63;
            As[l * K3_AS + e] = f2tf(xsrc[(size_t)l * DIQ + e0 + e]);
        }
        for (int idx = tid; idx < 40 * 64; idx += 256) {
            int r = idx >> 6, e = idx & 63;
            Ws[r * K3_WS + e] = (r < 38) ? f2tf(xpw[(size_t)r * DIQ + e0 + e]) : 0u;
        }
        __syncthreads();
        #pragma unroll
        for (int ks = 0; ks < 8; ks++) {
            int k0 = ks * 8;
            unsigned a0 = As[(wm + g) * K3_AS + k0 + tg];
            unsigned a1 = As[(wm + g + 8) * K3_AS + k0 + tg];
            unsigned a2 = As[(wm + g) * K3_AS + k0 + tg + 4];
            unsigned a3 = As[(wm + g + 8) * K3_AS + k0 + tg + 4];
            #pragma unroll
            for (int jf = 0; jf < 5; jf++) {
                int n = jf * 8 + g;
                unsigned b0 = Ws[n * K3_WS + k0 + tg];
                unsigned b1 = Ws[n * K3_WS + k0 + tg + 4];
                mma_tf32(acc[jf][0], acc[jf][1], acc[jf][2], acc[jf][3],
                         a0, a1, a2, a3, b0, b1);
            }
        }
    }
    __syncthreads();
    #pragma unroll
    for (int jf = 0; jf < 5; jf++) {
        int m = wm + g, n = jf * 8 + tg * 2;
        Db[m * 40 + n]           = acc[jf][0];
        Db[m * 40 + n + 1]       = acc[jf][1];
        Db[(m + 8) * 40 + n]     = acc[jf][2];
        Db[(m + 8) * 40 + n + 1] = acc[jf][3];
    }
    __syncthreads();

    // delta = softplus(dt @ dt_proj_w^T + b); store p1=exp(delta*A0), du=delta*u
    float2* pd = g_pd + ((size_t)b * LQ + l0) * DIQ;
    for (int idx = tid; idx < 128 * 192; idx += 256) {
        int l = idx / 192, e = idx - l * 192;
        float d = Bs[e];
        #pragma unroll
        for (int r = 0; r < 6; r++) d = fmaf(Db[l * 40 + r], Dt[e * 6 + r], d);
        float delta = softplusf(d);
        float u = xsrc[idx];
        float2 v;
        v.x = fexp(delta * A0s[e]);
        v.y = delta * u;
        pd[idx] = v;
    }
    // B, C
    float* bb = g_Bm + ((size_t)b * LQ + l0) * DSQ;
    float* cc = g_Cm + ((size_t)b * LQ + l0) * DSQ;
    for (int idx = tid; idx < 128 * 32; idx += 256) {
        int l = idx >> 5, n = idx & 31;
        float v = Db[l * 40 + 6 + n];
        if (n < 16) bb[(size_t)l * DSQ + n] = v;
        else        cc[(size_t)l * DSQ + (n - 16)] = v;
    }
}

// ================ K4: scan pass 1 (chunk-local h, P = prod p1) ================
__global__ __launch_bounds__(192) void mk_scan1(const float* __restrict__ alog) {
    __shared__ float4 sB[SCHQ][4];
    const int ch = blockIdx.x, b = blockIdx.y, e = threadIdx.x;
    const size_t off = (size_t)b * LQ + (size_t)ch * SCHQ;
    {
        const float4* gB = (const float4*)(g_Bm + off * DSQ);
        if (e < SCHQ * 4) ((float4*)sB)[e] = gB[e];
    }
    float a[DSQ];
    const bool pat = apat(alog, e, a);
    __syncthreads();

    float h[DSQ];
    #pragma unroll
    for (int n = 0; n < DSQ; n++) h[n] = 0.f;
    float P = 1.f;
    const float2* pd = g_pd + off * DIQ + e;

    if (pat) {
        #pragma unroll 4
        for (int s = 0; s < SCHQ; s++) {
            float2 v = pd[(size_t)s * DIQ];
            float4 q0 = sB[s][0], q1 = sB[s][1], q2 = sB[s][2], q3 = sB[s][3];
            float Bv[16] = {q0.x,q0.y,q0.z,q0.w, q1.x,q1.y,q1.z,q1.w,
                            q2.x,q2.y,q2.z,q2.w, q3.x,q3.y,q3.z,q3.w};
            float pw[16]; pw16f(v.x, pw);
            P *= v.x;
            #pragma unroll
            for (int n = 0; n < 16; n++) h[n] = fmaf(pw[n], h[n], v.y * Bv[n]);
        }
    } else {
        const float invA0 = 1.f / a[0];
        for (int s = 0; s < SCHQ; s++) {
            float2 v = pd[(size_t)s * DIQ];
            float4 q0 = sB[s][0], q1 = sB[s][1], q2 = sB[s][2], q3 = sB[s][3];
            float Bv[16] = {q0.x,q0.y,q0.z,q0.w, q1.x,q1.y,q1.z,q1.w,
                            q2.x,q2.y,q2.z,q2.w, q3.x,q3.y,q3.z,q3.w};
            float delta = __logf(v.x) * invA0;
            P *= v.x;
            #pragma unroll
            for (int n = 0; n < 16; n++) h[n] = fmaf(fexp(delta * a[n]), h[n], v.y * Bv[n]);
        }
    }
    float4* hd = (float4*)(g_hend + (((size_t)b * NCQ + ch) * DIQ + e) * DSQ);
    hd[0] = make_float4(h[0], h[1], h[2], h[3]);
    hd[1] = make_float4(h[4], h[5], h[6], h[7]);
    hd[2] = make_float4(h[8], h[9], h[10], h[11]);
    hd[3] = make_float4(h[12], h[13], h[14], h[15]);
    g_P[((size_t)b * NCQ + ch) * DIQ + e] = P;
}

// ================ K5: parallel combine (thread per (b,e,n)) ================
__global__ __launch_bounds__(256) void mk_comb(const float* __restrict__ alog) {
    const int idx = blockIdx.x * 256 + threadIdx.x;        // 24576 threads
    const int b = idx / (DIQ * DSQ);
    const int r = idx - b * (DIQ * DSQ);
    const int e = r >> 4, n = r & 15;

    const float A0 = -fexp(alog[e * DSQ]);
    const float an = -fexp(alog[e * DSQ + n]);
    const float tgt = (float)(n + 1) * A0;
    const bool pat = fabsf(an - tgt) <= 1e-4f * (1.f + fabsf(tgt));
    const float ratio = an / A0;
    const int m = n + 1;

    const float* pe = g_P    + (size_t)b * NCQ * DIQ + e;
    const float* he = g_hend + (size_t)b * NCQ * (DIQ * DSQ) + r;
    float*       hi = g_hin  + (size_t)b * NCQ * (DIQ * DSQ) + r;

    float h = 0.f;
    #pragma unroll 4
    for (int ch = 0; ch < NCQ; ch++) {
        float P  = pe[(size_t)ch * DIQ];
        float hd = he[(size_t)ch * (DIQ * DSQ)];
        hi[(size_t)ch * (DIQ * DSQ)] = h;
        float pw;
        if (pat) {
            float b2 = P * P, b4 = b2 * b2, b8 = b4 * b4;
            pw = ((m & 1) ? P : 1.f) * ((m & 2) ? b2 : 1.f)
               * ((m & 4) ? b4 : 1.f) * ((m & 8) ? b8 : 1.f);
        } else {
            pw = fexp(__logf(P) * ratio);
        }
        h = fmaf(pw, h, hd);
    }
}

// ================ K6: scan pass 2 (replay, emit y * silu(z)) ================
__global__ __launch_bounds__(192) void mk_scan2(const float* __restrict__ alog,
                                                const float* __restrict__ Dg) {
    __shared__ float4 sB[SCHQ][4];
    __shared__ float4 sC[SCHQ][4];
    const int ch = blockIdx.x, b = blockIdx.y, e = threadIdx.x;
    const size_t off = (size_t)b * LQ + (size_t)ch * SCHQ;
    {
        const float4* gB = (const float4*)(g_Bm + off * DSQ);
        const float4* gC = (const float4*)(g_Cm + off * DSQ);
        if (e < SCHQ * 4) { ((float4*)sB)[e] = gB[e]; ((float4*)sC)[e] = gC[e]; }
    }
    float a[DSQ];
    const bool pat = apat(alog, e, a);
    __syncthreads();

    float h[DSQ];
    {
        const float4* hi = (const float4*)(g_hin + (((size_t)b * NCQ + ch) * DIQ + e) * DSQ);
        float4 v0 = hi[0], v1 = hi[1], v2 = hi[2], v3 = hi[3];
        h[0]=v0.x; h[1]=v0.y; h[2]=v0.z; h[3]=v0.w;
        h[4]=v1.x; h[5]=v1.y; h[6]=v1.z; h[7]=v1.w;
        h[8]=v2.x; h[9]=v2.y; h[10]=v2.z; h[11]=v2.w;
        h[12]=v3.x; h[13]=v3.y; h[14]=v3.z; h[15]=v3.w;
    }
    const float Dv = Dg[e];
    const float2* pd = g_pd + off * DIQ + e;
    const float*  up = g_xms + off * DIQ + e;
    float*        zp = g_zs  + off * DIQ + e;

    if (pat) {
        #pragma unroll 4
        for (int s = 0; s < SCHQ; s++) {
            float2 v = pd[(size_t)s * DIQ];
            float  u = up[(size_t)s * DIQ];
            float4 q0 = sB[s][0], q1 = sB[s][1], q2 = sB[s][2], q3 = sB[s][3];
            float Bv[16] = {q0.x,q0.y,q0.z,q0.w, q1.x,q1.y,q1.z,q1.w,
                            q2.x,q2.y,q2.z,q2.w, q3.x,q3.y,q3.z,q3.w};
            float4 c0 = sC[s][0], c1 = sC[s][1], c2 = sC[s][2], c3 = sC[s][3];
            float Cv[16] = {c0.x,c0.y,c0.z,c0.w, c1.x,c1.y,c1.z,c1.w,
                            c2.x,c2.y,c2.z,c2.w, c3.x,c3.y,c3.z,c3.w};
            float pw[16]; pw16f(v.x, pw);
            float y = u * Dv;
            #pragma unroll
            for (int n = 0; n < 16; n++) {
                h[n] = fmaf(pw[n], h[n], v.y * Bv[n]);
                y = fmaf(h[n], Cv[n], y);
            }
            zp[(size_t)s * DIQ] = y * zp[(size_t)s * DIQ];
        }
    } else {
        const float invA0 = 1.f / a[0];
        for (int s = 0; s < SCHQ; s++) {
            float2 v = pd[(size_t)s * DIQ];
            float  u = up[(size_t)s * DIQ];
            float4 q0 = sB[s][0], q1 = sB[s][1], q2 = sB[s][2], q3 = sB[s][3];
            float Bv[16] = {q0.x,q0.y,q0.z,q0.w, q1.x,q1.y,q1.z,q1.w,
                            q2.x,q2.y,q2.z,q2.w, q3.x,q3.y,q3.z,q3.w};
            float4 c0 = sC[s][0], c1 = sC[s][1], c2 = sC[s][2], c3 = sC[s][3];
            float Cv[16] = {c0.x,c0.y,c0.z,c0.w, c1.x,c1.y,c1.z,c1.w,
                            c2.x,c2.y,c2.z,c2.w, c3.x,c3.y,c3.z,c3.w};
            float delta = __logf(v.x) * invA0;
            float y = u * Dv;
            #pragma unroll
            for (int n = 0; n < 16; n++) {
                h[n] = fmaf(fexp(delta * a[n]), h[n], v.y * Bv[n]);
                y = fmaf(h[n], Cv[n], y);
            }
            zp[(size_t)s * DIQ] = y * zp[(size_t)s * DIQ];
        }
    }
}

// ================ K7: out_proj (tf32 mma) + LayerNorm + transpose ================
#define K7_AS 68
#define K7_WS 68
__global__ __launch_bounds__(256) void mk_outln(const float* __restrict__ ow,
                                                const float* __restrict__ gam,
                                                const float* __restrict__ bet,
                                                float* __restrict__ out) {
    extern __shared__ unsigned sm_u[];
    unsigned* As = sm_u;
    unsigned* Ws = sm_u + 128 * K7_AS;
    float* Os = (float*)sm_u;
    float* Mu = (float*)(sm_u + 128 * K7_AS + 96 * K7_WS);
    float* Rs = Mu + 128;
    const int l0 = blockIdx.x * 128, b = blockIdx.y, tid = threadIdx.x;

    const int warp = tid >> 5, lane = tid & 31, g = lane >> 2, tg = lane & 3;
    const int wm = (warp & 3) * 32, wn = (warp >> 2) * 48;

    float acc[2][6][4];
    #pragma unroll
    for (int i = 0; i < 2; i++)
        #pragma unroll
        for (int jf = 0; jf < 6; jf++)
            #pragma unroll
            for (int q = 0; q < 4; q++) acc[i][jf][q] = 0.f;

    const float* ysrc = g_zs + ((size_t)b * LQ + l0) * DIQ;
    for (int kc = 0; kc < 3; kc++) {
        int e0 = kc * 64;
        __syncthreads();
        for (int idx = tid; idx < 128 * 64; idx += 256) {
            int l = idx >> 6, e = idx & 63;
            As[l * K7_AS + e] = f2tf(ysrc[(size_t)l * DIQ + e0 + e]);
        }
        for (int idx = tid; idx < 96 * 64; idx += 256) {
            int o = idx >> 6, e = idx & 63;
            Ws[o * K7_WS + e] = f2tf(ow[(size_t)o * DIQ + e0 + e]);
        }
        __syncthreads();
        #pragma unroll
        for (int ks = 0; ks < 8; ks++) {
            int k0 = ks * 8;
            unsigned a[2][4];
            #pragma unroll
            for (int i = 0; i < 2; i++) {
                int m = wm + i * 16;
                a[i][0] = As[(m + g) * K7_AS + k0 + tg];
                a[i][1] = As[(m + g + 8) * K7_AS + k0 + tg];
                a[i][2] = As[(m + g) * K7_AS + k0 + tg + 4];
                a[i][3] = As[(m + g + 8) * K7_AS + k0 + tg + 4];
            }
            #pragma unroll
            for (int jf = 0; jf < 6; jf++) {
                int n = wn + jf * 8 + g;
                unsigned b0 = Ws[n * K7_WS + k0 + tg];
                unsigned b1 = Ws[n * K7_WS + k0 + tg + 4];
                #pragma unroll
                for (int i = 0; i < 2; i++)
                    mma_tf32(acc[i][jf][0], acc[i][jf][1], acc[i][jf][2], acc[i][jf][3],
                             a[i][0], a[i][1], a[i][2], a[i][3], b0, b1);
            }
        }
    }
    __syncthreads();
    #pragma unroll
    for (int i = 0; i < 2; i++)
        #pragma unroll
        for (int jf = 0; jf < 6; jf++) {
            int m = wm + i * 16 + g, n = wn + jf * 8 + tg * 2;
            Os[m * 100 + n]           = acc[i][jf][0];
            Os[m * 100 + n + 1]       = acc[i][jf][1];
            Os[(m + 8) * 100 + n]     = acc[i][jf][2];
            Os[(m + 8) * 100 + n + 1] = acc[i][jf][3];
        }
    __syncthreads();

    if (tid < 128) {
        float s = 0.f;
        for (int o = 0; o < 96; o++) s += Os[tid * 100 + o];
        float mu = s * (1.f / 96.f);
        float v = 0.f;
        for (int o = 0; o < 96; o++) { float d = Os[tid * 100 + o] - mu; v = fmaf(d, d, v); }
        Mu[tid] = mu;
        Rs[tid] = rsqrtf(v * (1.f / 96.f) + 1e-5f);
    }
    __syncthreads();

    float* ob = out + (size_t)b * CQ * LQ + l0;
    for (int idx = tid; idx < 96 * 128; idx += 256) {
        int o = idx >> 7, l = idx & 127;
        ob[(size_t)o * LQ + l] = (Os[l * 100 + o] - Mu[l]) * Rs[l] * gam[o] + bet[o];
    }
}

// ================ launch ================
extern "C" void kernel_launch(void* const* d_in, const int* in_sizes, int n_in,
                              void* d_out, int out_size) {
    const float* x    = (const float*)d_in[0];
    const float* inw  = (const float*)d_in[1];
    const float* cw   = (const float*)d_in[2];
    const float* cb   = (const float*)d_in[3];
    const float* xpw  = (const float*)d_in[4];
    const float* dtw  = (const float*)d_in[5];
    const float* dtb  = (const float*)d_in[6];
    const float* alog = (const float*)d_in[7];
    const float* Dg   = (const float*)d_in[8];
    const float* ow   = (const float*)d_in[9];
    const float* gam  = (const float*)d_in[10];
    const float* bet  = (const float*)d_in[11];
    float* out = (float*)d_out;

    const int SMEM1 = (96 * K1_AS + 64 * K1_WS) * 4;
    const int SMEM3 = (128 * K3_AS + 40 * K3_WS + 128 * 40 + 192 * 6 + 192 + 192) * 4;
    const int SMEM7 = (128 * K7_AS + 96 * K7_WS + 256) * 4;

    cudaFuncSetAttribute(mk_inproj, cudaFuncAttributeMaxDynamicSharedMemorySize, SMEM1);
    cudaFuncSetAttribute(mk_xproj,  cudaFuncAttributeMaxDynamicSharedMemorySize, SMEM3);
    cudaFuncSetAttribute(mk_outln,  cudaFuncAttributeMaxDynamicSharedMemorySize, SMEM7);

    mk_inproj<<<dim3(LQ / 128, DI2Q / 64, BQ), 256, SMEM1>>>(x, inw);
    mk_conv  <<<dim3(LQ / 32, DIQ / 32, BQ), dim3(32, 8)>>>(cw, cb);
    mk_xproj <<<dim3(LQ / 128, BQ), 256, SMEM3>>>(xpw, dtw, dtb, alog);
    mk_scan1 <<<dim3(NCQ, BQ), DIQ>>>(alog);
    mk_comb  <<<(BQ * DIQ * DSQ) / 256, 256>>>(alog);
    mk_scan2 <<<dim3(NCQ, BQ), DIQ>>>(alog, Dg);
    mk_outln <<<dim3(LQ / 128, BQ), 256, SMEM7>>>(ow, gam, bet, out);
}